// round 8
// baseline (speedup 1.0000x reference)
#include <cuda_runtime.h>
#include <cstdint>

namespace {
constexpr int Bsz    = 16384;
constexpr int Ncap   = 32;
constexpr int Din    = 128;
constexpr int Dout   = 256;
constexpr int RITERS = 3;
constexpr int UNITS  = Bsz / 2;

// shared memory layout (float offsets)
constexpr int OFF_W    = 0;                  // 32768 floats (W fragments, tf32)
constexpr int OFF_A    = OFF_W + 32768;      // per-half: 64 rows * 132 = 8448; x2
constexpr int OFF_BIAS = OFF_A + 2 * 8448;   // 256
constexpr int OFF_SCR  = OFF_BIAS + 256;     // per-half scratch
// scratch offsets within a half
constexpr int S_NRM  = 0;      // [2][32][4] = 256
constexpr int S_BIJ0 = 256;    // 64
constexpr int S_BIJ1 = 320;    // 64
constexpr int S_V    = 384;    // [2][256] = 512
constexpr int S_SQP0 = 896;    // 16
constexpr int S_SQP1 = 912;    // 16
constexpr int S_AGR0 = 928;    // 256
constexpr int S_AGR1 = 1184;   // 256
constexpr int SCR_SIZE = 1440;
constexpr int SMEM_FLOATS = OFF_SCR + 2 * SCR_SIZE;
constexpr int SMEM_BYTES  = SMEM_FLOATS * 4;   // ~211 KB
}

__device__ __forceinline__ float to_tf32(float x) {
    float y;
    asm("cvt.rna.tf32.f32 %0, %1;" : "=f"(y) : "f"(x));
    return y;
}

__device__ __forceinline__ void bar_half(int half) {
    asm volatile("bar.sync %0, 256;" :: "r"(1 + half) : "memory");
}

__device__ __forceinline__ void cp_async16(uint32_t saddr, const void* gptr) {
    asm volatile("cp.async.cg.shared.global [%0], [%1], 16;\n"
                 :: "r"(saddr), "l"(gptr));
}
__device__ __forceinline__ void cp_commit() {
    asm volatile("cp.async.commit_group;\n" ::: "memory");
}
__device__ __forceinline__ void cp_wait0() {
    asm volatile("cp.async.wait_group 0;\n" ::: "memory");
}

// A operand registers carry raw fp32 bits; tf32 MMA reads bits[31:13] (RZ).
__device__ __forceinline__ void mma_tf32(float* c, const float* a, float b0, float b1) {
    asm volatile(
        "mma.sync.aligned.m16n8k8.row.col.f32.tf32.tf32.f32 "
        "{%0,%1,%2,%3}, {%4,%5,%6,%7}, {%8,%9}, {%0,%1,%2,%3};\n"
        : "+f"(c[0]), "+f"(c[1]), "+f"(c[2]), "+f"(c[3])
        : "r"(__float_as_uint(a[0])), "r"(__float_as_uint(a[1])),
          "r"(__float_as_uint(a[2])), "r"(__float_as_uint(a[3])),
          "r"(__float_as_uint(b0)), "r"(__float_as_uint(b1)));
}

__global__ void __launch_bounds__(512, 1)
dyr_agg_kernel(const float* __restrict__ embeds,
               const float* __restrict__ weights,
               const float* __restrict__ Wg,
               const float* __restrict__ bg,
               float* __restrict__ out)
{
    extern __shared__ float sm[];
    const int tid  = threadIdx.x;
    const int half = tid >> 8;       // 0 or 1: independent 256-thread worker
    const int htid = tid & 255;
    const int lane = tid & 31;
    const int wh   = (tid >> 5) & 7; // warp-in-half 0..7
    const int cg   = wh & 3;         // column group: 64 cols at cg*64
    const int rg   = wh >> 2;        // which batch of the pair
    const int qr   = lane >> 2;      // 0..7
    const int qc   = lane & 3;       // 0..3

    float* scr = sm + OFF_SCR + half * SCR_SIZE;
    float* As  = sm + OFF_A + half * 8448;
    const uint32_t As_u32  = (uint32_t)__cvta_generic_to_shared(As);
    const uint32_t scr_u32 = (uint32_t)__cvta_generic_to_shared(scr);

    // ---- issue async copy of this half's FIRST unit (overlaps W staging) ----
    int unit0 = blockIdx.x * 2 + half;
    if (unit0 < UNITS) {
        const float4* eg = (const float4*)(embeds + (size_t)unit0 * 2 * Ncap * Din);
        #pragma unroll
        for (int t = 0; t < 8; t++) {
            int i   = htid + t * 256;
            int row = i >> 5, j4 = i & 31;
            cp_async16(As_u32 + (row * 132 + j4 * 4) * 4, eg + i);
        }
        if (htid < 16)   // 64 floats of routing logits -> slot 0
            cp_async16(scr_u32 + (S_BIJ0 + htid * 4) * 4,
                       weights + (size_t)unit0 * 64 + htid * 4);
    }
    cp_commit();

    // ---- stage W (paired-j, k-permuted layout) + bias, whole CTA, once ----
    // k-permutation within each k8 block: logical l<4 -> phys 2l; l>=4 -> 2(l-4)+1.
    // Same permutation is implied by the A-side float2 loads in the GEMM.
    for (int idx = tid; idx < 16 * 16 * 32; idx += 512) {
        int nt2 = idx >> 9;
        int ks  = (idx >> 5) & 15;
        int ln  = idx & 31;
        int p0  = ks * 8 + 2 * (ln & 3);   // phys rows p0 (logical ln&3), p0+1 (logical (ln&3)+4)
        int n0  = nt2 * 16 + (ln >> 2);
        sm[OFF_W + idx * 4 + 0] = to_tf32(Wg[p0 * Dout + n0]);
        sm[OFF_W + idx * 4 + 1] = to_tf32(Wg[(p0 + 1) * Dout + n0]);
        sm[OFF_W + idx * 4 + 2] = to_tf32(Wg[p0 * Dout + n0 + 8]);
        sm[OFF_W + idx * 4 + 3] = to_tf32(Wg[(p0 + 1) * Dout + n0 + 8]);
    }
    if (tid < Dout) sm[OFF_BIAS + tid] = bg[tid];
    __syncthreads();

    float* out_poses = out;
    float* out_c     = out + (size_t)Bsz * Dout;

    const int stride = gridDim.x * 2;
    int p = 0;  // b_ij slot parity (per loop iteration)
    for (int unit = unit0; unit < UNITS; unit += stride, p ^= 1) {
        const int  b0       = unit * 2;
        const int  nunit    = unit + stride;
        const bool has_next = nunit < UNITS;
        const int  BIJ      = p ? S_BIJ1 : S_BIJ0;
        const int  BIJN     = p ? S_BIJ0 : S_BIJ1;

        // A + b_ij for this unit were issued last iteration (or prologue)
        cp_wait0();
        bar_half(half);   // [bar 1] visible to all warps of this half

        // routing logits for this warp's batch, register-resident (lane = capsule n)
        float bij = scr[BIJ + rg * 32 + lane];

        // ---- GEMM: each warp computes 32 rows (rg) x 64 cols (cg) ----
        float c[2][8][4];
        #pragma unroll
        for (int mt = 0; mt < 2; mt++)
            #pragma unroll
            for (int j = 0; j < 8; j++)
                #pragma unroll
                for (int q = 0; q < 4; q++) c[mt][j][q] = 0.0f;

        #pragma unroll
        for (int ks = 0; ks < 16; ks++) {
            float a[2][4];
            #pragma unroll
            for (int mt = 0; mt < 2; mt++) {
                const float* ar = As + (rg * 32 + mt * 16) * 132 + ks * 8 + 2 * qc;
                float2 f0 = *(const float2*)&ar[qr * 132];
                float2 f1 = *(const float2*)&ar[(qr + 8) * 132];
                a[mt][0] = f0.x; a[mt][1] = f1.x;   // logical col qc
                a[mt][2] = f0.y; a[mt][3] = f1.y;   // logical col qc+4
            }
            #pragma unroll
            for (int jp = 0; jp < 4; jp++) {
                float4 b4 = *(const float4*)&sm[OFF_W + (((cg * 4 + jp) * 16 + ks) * 32 + lane) * 4];
                mma_tf32(c[0][2 * jp + 0], a[0], b4.x, b4.y);
                mma_tf32(c[1][2 * jp + 0], a[1], b4.x, b4.y);
                mma_tf32(c[0][2 * jp + 1], a[0], b4.z, b4.w);
                mma_tf32(c[1][2 * jp + 1], a[1], b4.z, b4.w);
            }
        }

        // ---- bias add + per-row squared-norm partials ----
        float pn[2][2] = {{0.f, 0.f}, {0.f, 0.f}};
        #pragma unroll
        for (int mt = 0; mt < 2; mt++)
            #pragma unroll
            for (int j = 0; j < 8; j++)
                #pragma unroll
                for (int q = 0; q < 4; q++) {
                    int pq = q & 1, h = q >> 1;
                    int col = cg * 64 + j * 8 + qc * 2 + pq;
                    float v = c[mt][j][q] + sm[OFF_BIAS + col];
                    c[mt][j][q] = v;
                    pn[mt][h] += v * v;
                }
        #pragma unroll
        for (int mt = 0; mt < 2; mt++)
            #pragma unroll
            for (int h = 0; h < 2; h++) {
                pn[mt][h] += __shfl_xor_sync(0xffffffffu, pn[mt][h], 1);
                pn[mt][h] += __shfl_xor_sync(0xffffffffu, pn[mt][h], 2);
            }
        if (qc == 0) {
            #pragma unroll
            for (int mt = 0; mt < 2; mt++)
                #pragma unroll
                for (int h = 0; h < 2; h++) {
                    int n = mt * 16 + qr + h * 8;
                    scr[S_NRM + rg * 128 + n * 4 + cg] = pn[mt][h];
                }
        }
        bar_half(half);   // [bar 2] GEMM reads of A done; norm partials visible

        // ---- A buffer now dead: issue next unit's async copies (overlap routing) ----
        if (has_next) {
            const float4* eg = (const float4*)(embeds + (size_t)nunit * 2 * Ncap * Din);
            #pragma unroll
            for (int t = 0; t < 8; t++) {
                int i   = htid + t * 256;
                int row = i >> 5, j4 = i & 31;
                cp_async16(As_u32 + (row * 132 + j4 * 4) * 4, eg + i);
            }
            if (htid < 16)
                cp_async16(scr_u32 + (BIJN + htid * 4) * 4,
                           weights + (size_t)nunit * 64 + htid * 4);
        }
        cp_commit();

        // ---- normalize u_hat fragments (inv computed redundantly per thread) ----
        #pragma unroll
        for (int mt = 0; mt < 2; mt++)
            #pragma unroll
            for (int h = 0; h < 2; h++) {
                int n = mt * 16 + qr + h * 8;
                float4 pr = *(const float4*)&scr[S_NRM + rg * 128 + n * 4];
                float s   = pr.x + pr.y + pr.z + pr.w;
                float inv = rsqrtf(fmaxf(s, 1e-24f));   // == 1/max(sqrt(s),1e-12)
                #pragma unroll
                for (int j = 0; j < 8; j++) {
                    c[mt][j][2 * h + 0] *= inv;
                    c[mt][j][2 * h + 1] *= inv;
                }
            }

        // ---- dynamic routing: ONE barrier per iteration ----
        float cval = 0.0f;
        #pragma unroll 1
        for (int it = 0; it < RITERS; it++) {
            const int SQP = (it & 1) ? S_SQP1 : S_SQP0;
            const int AGR = (it & 1) ? S_AGR1 : S_AGR0;

            // softmax over capsules, redundant in every warp (lane = n)
            float m = bij;
            #pragma unroll
            for (int off = 16; off; off >>= 1)
                m = fmaxf(m, __shfl_xor_sync(0xffffffffu, m, off));
            float e = __expf(bij - m);
            float ssum = e;
            #pragma unroll
            for (int off = 16; off; off >>= 1)
                ssum += __shfl_xor_sync(0xffffffffu, ssum, off);
            cval = e * (32.0f / ssum);

            float cv0 = __shfl_sync(0xffffffffu, cval, qr);
            float cv1 = __shfl_sync(0xffffffffu, cval, qr + 8);
            float cv2 = __shfl_sync(0xffffffffu, cval, qr + 16);
            float cv3 = __shfl_sync(0xffffffffu, cval, qr + 24);

            // s[d] = sum_n c[n] * u_hat[n][d], from fragments
            float sp[8][2];
            #pragma unroll
            for (int j = 0; j < 8; j++) {
                sp[j][0] = cv0 * c[0][j][0] + cv1 * c[0][j][2]
                         + cv2 * c[1][j][0] + cv3 * c[1][j][2];
                sp[j][1] = cv0 * c[0][j][1] + cv1 * c[0][j][3]
                         + cv2 * c[1][j][1] + cv3 * c[1][j][3];
            }
            #pragma unroll
            for (int j = 0; j < 8; j++)
                #pragma unroll
                for (int pp = 0; pp < 2; pp++) {
                    sp[j][pp] += __shfl_xor_sync(0xffffffffu, sp[j][pp], 4);
                    sp[j][pp] += __shfl_xor_sync(0xffffffffu, sp[j][pp], 8);
                    sp[j][pp] += __shfl_xor_sync(0xffffffffu, sp[j][pp], 16);
                }

            // warp-partial sum(s^2) over this warp's 64 cols
            float qs = 0.0f;
            #pragma unroll
            for (int j = 0; j < 8; j++)
                qs += sp[j][0] * sp[j][0] + sp[j][1] * sp[j][1];
            qs += __shfl_xor_sync(0xffffffffu, qs, 1);
            qs += __shfl_xor_sync(0xffffffffu, qs, 2);
            if (lane == 0) scr[SQP + rg * 4 + cg] = qs;

            if (it < RITERS - 1) {
                // UNSCALED agree partials (scale applied after the barrier)
                float ap[2][2] = {{0.f, 0.f}, {0.f, 0.f}};
                #pragma unroll
                for (int j = 0; j < 8; j++) {
                    float s0 = sp[j][0], s1 = sp[j][1];
                    ap[0][0] += c[0][j][0] * s0 + c[0][j][1] * s1;
                    ap[0][1] += c[0][j][2] * s0 + c[0][j][3] * s1;
                    ap[1][0] += c[1][j][0] * s0 + c[1][j][1] * s1;
                    ap[1][1] += c[1][j][2] * s0 + c[1][j][3] * s1;
                }
                #pragma unroll
                for (int mt = 0; mt < 2; mt++)
                    #pragma unroll
                    for (int h = 0; h < 2; h++) {
                        float a = ap[mt][h];
                        a += __shfl_xor_sync(0xffffffffu, a, 1);
                        a += __shfl_xor_sync(0xffffffffu, a, 2);
                        if (qc == 0) {
                            int n = mt * 16 + qr + h * 8;
                            scr[AGR + rg * 128 + n * 4 + cg] = a;
                        }
                    }
            }
            bar_half(half);   // [one bar per iteration]

            float4 q4 = *(const float4*)&scr[SQP + rg * 4];
            float t4 = q4.x + q4.y + q4.z + q4.w;
            float scale = t4 / ((1.0f + t4) * sqrtf(t4 + 1e-9f));

            if (it < RITERS - 1) {
                // every warp updates its register b_ij itself (redundant, consistent)
                float4 ag = *(const float4*)&scr[AGR + rg * 128 + lane * 4];
                bij += scale * (ag.x + ag.y + ag.z + ag.w);
            } else {
                // final iter: stage v into smem for coalesced output
                #pragma unroll
                for (int j = 0; j < 8; j++)
                    if (qr == j) {
                        float2 vv = make_float2(scale * sp[j][0], scale * sp[j][1]);
                        *(float2*)&scr[S_V + rg * 256 + cg * 64 + j * 8 + qc * 2] = vv;
                    }
            }
        }

        bar_half(half);   // v staged
        out_poses[(size_t)b0 * Dout + htid]       = scr[S_V + htid];
        out_poses[(size_t)(b0 + 1) * Dout + htid] = scr[S_V + 256 + htid];
        if (cg == 0)
            out_c[(size_t)(b0 + rg) * Ncap + lane] = cval;
        // no trailing barrier needed: next writes to S_V/S_NRM happen only after
        // the next unit's own barriers, which all warps reach after these reads.
    }
}

extern "C" void kernel_launch(void* const* d_in, const int* in_sizes, int n_in,
                              void* d_out, int out_size) {
    const float* embeds  = (const float*)d_in[0];
    const float* weights = (const float*)d_in[1];
    const float* Wg      = (const float*)d_in[2];
    const float* bg      = (const float*)d_in[3];
    float* out = (float*)d_out;

    cudaFuncSetAttribute(dyr_agg_kernel,
                         cudaFuncAttributeMaxDynamicSharedMemorySize, SMEM_BYTES);
    int sms = 148;
    cudaDeviceGetAttribute(&sms, cudaDevAttrMultiProcessorCount, 0);
    dyr_agg_kernel<<<sms, 512, SMEM_BYTES>>>(embeds, weights, Wg, bg, out);
}

// round 10
// speedup vs baseline: 1.0591x; 1.0591x over previous
#include <cuda_runtime.h>
#include <cstdint>

namespace {
constexpr int Bsz    = 16384;
constexpr int Ncap   = 32;
constexpr int Din    = 128;
constexpr int Dout   = 256;
constexpr int RITERS = 3;
constexpr int UNITS  = Bsz / 2;

constexpr int A_STRIDE = 136;   // floats per row; 136 ≡ 8 (mod 32) -> conflict-free LDS.64
constexpr int A_HALF   = 64 * A_STRIDE;   // 8704 floats per half

// shared memory layout (float offsets)
constexpr int OFF_W    = 0;                  // 32768 floats (W fragments, tf32, k-permuted)
constexpr int OFF_A    = OFF_W + 32768;      // per-half: A_HALF; x2
constexpr int OFF_BIAS = OFF_A + 2 * A_HALF; // 256
constexpr int OFF_SCR  = OFF_BIAS + 256;     // per-half scratch
// scratch offsets within a half
constexpr int S_NRM  = 0;      // [2][32][4] = 256
constexpr int S_BIJ0 = 256;    // 64
constexpr int S_BIJ1 = 320;    // 64
constexpr int S_V    = 384;    // [2][256] = 512
constexpr int S_SQP0 = 896;    // 16
constexpr int S_SQP1 = 912;    // 16
constexpr int S_AGR0 = 928;    // 256
constexpr int S_AGR1 = 1184;   // 256
constexpr int SCR_SIZE = 1440;
constexpr int SMEM_FLOATS = OFF_SCR + 2 * SCR_SIZE;
constexpr int SMEM_BYTES  = SMEM_FLOATS * 4;   // ~213 KB
}

__device__ __forceinline__ float to_tf32(float x) {
    float y;
    asm("cvt.rna.tf32.f32 %0, %1;" : "=f"(y) : "f"(x));
    return y;
}

__device__ __forceinline__ void bar_half(int half) {
    asm volatile("bar.sync %0, 256;" :: "r"(1 + half) : "memory");
}

__device__ __forceinline__ void cp_async16(uint32_t saddr, const void* gptr) {
    asm volatile("cp.async.cg.shared.global [%0], [%1], 16;\n"
                 :: "r"(saddr), "l"(gptr));
}
__device__ __forceinline__ void cp_commit() {
    asm volatile("cp.async.commit_group;\n" ::: "memory");
}
__device__ __forceinline__ void cp_wait0() {
    asm volatile("cp.async.wait_group 0;\n" ::: "memory");
}

// A operand registers carry raw fp32 bits; tf32 MMA reads bits[31:13] (RZ).
__device__ __forceinline__ void mma_tf32(float* c, const float* a, float b0, float b1) {
    asm volatile(
        "mma.sync.aligned.m16n8k8.row.col.f32.tf32.tf32.f32 "
        "{%0,%1,%2,%3}, {%4,%5,%6,%7}, {%8,%9}, {%0,%1,%2,%3};\n"
        : "+f"(c[0]), "+f"(c[1]), "+f"(c[2]), "+f"(c[3])
        : "r"(__float_as_uint(a[0])), "r"(__float_as_uint(a[1])),
          "r"(__float_as_uint(a[2])), "r"(__float_as_uint(a[3])),
          "r"(__float_as_uint(b0)), "r"(__float_as_uint(b1)));
}

__global__ void __launch_bounds__(512, 1)
dyr_agg_kernel(const float* __restrict__ embeds,
               const float* __restrict__ weights,
               const float* __restrict__ Wg,
               const float* __restrict__ bg,
               float* __restrict__ out)
{
    extern __shared__ float sm[];
    const int tid  = threadIdx.x;
    const int half = tid >> 8;       // 0 or 1: independent 256-thread worker
    const int htid = tid & 255;
    const int lane = tid & 31;
    const int wh   = (tid >> 5) & 7; // warp-in-half 0..7
    const int cg   = wh & 3;         // column group: 64 cols at cg*64
    const int rg   = wh >> 2;        // which batch of the pair
    const int qr   = lane >> 2;      // 0..7
    const int qc   = lane & 3;       // 0..3

    float* scr = sm + OFF_SCR + half * SCR_SIZE;
    float* As  = sm + OFF_A + half * A_HALF;
    const uint32_t As_u32  = (uint32_t)__cvta_generic_to_shared(As);
    const uint32_t scr_u32 = (uint32_t)__cvta_generic_to_shared(scr);

    // ---- issue async copy of this half's FIRST unit (overlaps W staging) ----
    int unit0 = blockIdx.x * 2 + half;
    if (unit0 < UNITS) {
        const float4* eg = (const float4*)(embeds + (size_t)unit0 * 2 * Ncap * Din);
        #pragma unroll
        for (int t = 0; t < 8; t++) {
            int i   = htid + t * 256;
            int row = i >> 5, j4 = i & 31;
            cp_async16(As_u32 + (row * A_STRIDE + j4 * 4) * 4, eg + i);
        }
        if (htid < 16)   // 64 floats of routing logits -> slot 0
            cp_async16(scr_u32 + (S_BIJ0 + htid * 4) * 4,
                       weights + (size_t)unit0 * 64 + htid * 4);
    }
    cp_commit();

    // ---- stage W (paired-j, k-permuted layout) + bias, whole CTA, once ----
    // k-permutation within each k8 block: logical l<4 -> phys 2l; l>=4 -> 2(l-4)+1.
    // Same permutation is implied by the A-side float2 loads in the GEMM.
    for (int idx = tid; idx < 16 * 16 * 32; idx += 512) {
        int nt2 = idx >> 9;
        int ks  = (idx >> 5) & 15;
        int ln  = idx & 31;
        int p0  = ks * 8 + 2 * (ln & 3);   // phys rows p0 (logical ln&3), p0+1 (logical (ln&3)+4)
        int n0  = nt2 * 16 + (ln >> 2);
        sm[OFF_W + idx * 4 + 0] = to_tf32(Wg[p0 * Dout + n0]);
        sm[OFF_W + idx * 4 + 1] = to_tf32(Wg[(p0 + 1) * Dout + n0]);
        sm[OFF_W + idx * 4 + 2] = to_tf32(Wg[p0 * Dout + n0 + 8]);
        sm[OFF_W + idx * 4 + 3] = to_tf32(Wg[(p0 + 1) * Dout + n0 + 8]);
    }
    if (tid < Dout) sm[OFF_BIAS + tid] = bg[tid];
    __syncthreads();

    float* out_poses = out;
    float* out_c     = out + (size_t)Bsz * Dout;

    const int stride = gridDim.x * 2;
    int p = 0;  // b_ij slot parity (per loop iteration)
    for (int unit = unit0; unit < UNITS; unit += stride, p ^= 1) {
        const int  b0       = unit * 2;
        const int  nunit    = unit + stride;
        const bool has_next = nunit < UNITS;
        const int  BIJ      = p ? S_BIJ1 : S_BIJ0;
        const int  BIJN     = p ? S_BIJ0 : S_BIJ1;

        // A + b_ij for this unit were issued last iteration (or prologue)
        cp_wait0();
        bar_half(half);   // [bar 1] visible to all warps of this half

        // routing logits for this warp's batch, register-resident (lane = capsule n)
        float bij = scr[BIJ + rg * 32 + lane];

        // ---- GEMM: each warp computes 32 rows (rg) x 64 cols (cg) ----
        float c[2][8][4];
        #pragma unroll
        for (int mt = 0; mt < 2; mt++)
            #pragma unroll
            for (int j = 0; j < 8; j++)
                #pragma unroll
                for (int q = 0; q < 4; q++) c[mt][j][q] = 0.0f;

        #pragma unroll
        for (int ks = 0; ks < 16; ks++) {
            float a[2][4];
            #pragma unroll
            for (int mt = 0; mt < 2; mt++) {
                const float* ar = As + (rg * 32 + mt * 16) * A_STRIDE + ks * 8 + 2 * qc;
                float2 f0 = *(const float2*)&ar[qr * A_STRIDE];
                float2 f1 = *(const float2*)&ar[(qr + 8) * A_STRIDE];
                a[mt][0] = f0.x; a[mt][1] = f1.x;   // logical col qc
                a[mt][2] = f0.y; a[mt][3] = f1.y;   // logical col qc+4
            }
            #pragma unroll
            for (int jp = 0; jp < 4; jp++) {
                float4 b4 = *(const float4*)&sm[OFF_W + (((cg * 4 + jp) * 16 + ks) * 32 + lane) * 4];
                mma_tf32(c[0][2 * jp + 0], a[0], b4.x, b4.y);
                mma_tf32(c[1][2 * jp + 0], a[1], b4.x, b4.y);
                mma_tf32(c[0][2 * jp + 1], a[0], b4.z, b4.w);
                mma_tf32(c[1][2 * jp + 1], a[1], b4.z, b4.w);
            }
        }

        // ---- bias add + per-row squared-norm partials ----
        float pn[2][2] = {{0.f, 0.f}, {0.f, 0.f}};
        #pragma unroll
        for (int mt = 0; mt < 2; mt++)
            #pragma unroll
            for (int j = 0; j < 8; j++)
                #pragma unroll
                for (int q = 0; q < 4; q++) {
                    int pq = q & 1, h = q >> 1;
                    int col = cg * 64 + j * 8 + qc * 2 + pq;
                    float v = c[mt][j][q] + sm[OFF_BIAS + col];
                    c[mt][j][q] = v;
                    pn[mt][h] += v * v;
                }
        #pragma unroll
        for (int mt = 0; mt < 2; mt++)
            #pragma unroll
            for (int h = 0; h < 2; h++) {
                pn[mt][h] += __shfl_xor_sync(0xffffffffu, pn[mt][h], 1);
                pn[mt][h] += __shfl_xor_sync(0xffffffffu, pn[mt][h], 2);
            }
        if (qc == 0) {
            #pragma unroll
            for (int mt = 0; mt < 2; mt++)
                #pragma unroll
                for (int h = 0; h < 2; h++) {
                    int n = mt * 16 + qr + h * 8;
                    scr[S_NRM + rg * 128 + n * 4 + cg] = pn[mt][h];
                }
        }
        bar_half(half);   // [bar 2] GEMM reads of A done; norm partials visible

        // ---- A buffer now dead: issue next unit's async copies (overlap routing) ----
        if (has_next) {
            const float4* eg = (const float4*)(embeds + (size_t)nunit * 2 * Ncap * Din);
            #pragma unroll
            for (int t = 0; t < 8; t++) {
                int i   = htid + t * 256;
                int row = i >> 5, j4 = i & 31;
                cp_async16(As_u32 + (row * A_STRIDE + j4 * 4) * 4, eg + i);
            }
            if (htid < 16)
                cp_async16(scr_u32 + (BIJN + htid * 4) * 4,
                           weights + (size_t)nunit * 64 + htid * 4);
        }
        cp_commit();

        // ---- normalize u_hat fragments (inv computed redundantly per thread) ----
        #pragma unroll
        for (int mt = 0; mt < 2; mt++)
            #pragma unroll
            for (int h = 0; h < 2; h++) {
                int n = mt * 16 + qr + h * 8;
                float4 pr = *(const float4*)&scr[S_NRM + rg * 128 + n * 4];
                float s   = pr.x + pr.y + pr.z + pr.w;
                float inv = rsqrtf(fmaxf(s, 1e-24f));   // == 1/max(sqrt(s),1e-12)
                #pragma unroll
                for (int j = 0; j < 8; j++) {
                    c[mt][j][2 * h + 0] *= inv;
                    c[mt][j][2 * h + 1] *= inv;
                }
            }

        // ---- dynamic routing: ONE barrier per iteration ----
        float cval = 0.0f;
        #pragma unroll 1
        for (int it = 0; it < RITERS; it++) {
            const int SQP = (it & 1) ? S_SQP1 : S_SQP0;
            const int AGR = (it & 1) ? S_AGR1 : S_AGR0;

            // softmax over capsules, redundant in every warp (lane = n).
            // No max-shift: |b_ij| <= ~6.5 (weights ~N(0,1), |agree|<=1 per iter),
            // exp is safely in fp32 range; softmax is shift-invariant.
            float e = __expf(bij);
            float ssum = e;
            #pragma unroll
            for (int off = 16; off; off >>= 1)
                ssum += __shfl_xor_sync(0xffffffffu, ssum, off);
            cval = e * (32.0f / ssum);

            float cv0 = __shfl_sync(0xffffffffu, cval, qr);
            float cv1 = __shfl_sync(0xffffffffu, cval, qr + 8);
            float cv2 = __shfl_sync(0xffffffffu, cval, qr + 16);
            float cv3 = __shfl_sync(0xffffffffu, cval, qr + 24);

            // s[d] = sum_n c[n] * u_hat[n][d], from fragments
            float sp[8][2];
            #pragma unroll
            for (int j = 0; j < 8; j++) {
                sp[j][0] = cv0 * c[0][j][0] + cv1 * c[0][j][2]
                         + cv2 * c[1][j][0] + cv3 * c[1][j][2];
                sp[j][1] = cv0 * c[0][j][1] + cv1 * c[0][j][3]
                         + cv2 * c[1][j][1] + cv3 * c[1][j][3];
            }
            #pragma unroll
            for (int j = 0; j < 8; j++)
                #pragma unroll
                for (int pp = 0; pp < 2; pp++) {
                    sp[j][pp] += __shfl_xor_sync(0xffffffffu, sp[j][pp], 4);
                    sp[j][pp] += __shfl_xor_sync(0xffffffffu, sp[j][pp], 8);
                    sp[j][pp] += __shfl_xor_sync(0xffffffffu, sp[j][pp], 16);
                }

            // warp-partial sum(s^2) over this warp's 64 cols
            float qs = 0.0f;
            #pragma unroll
            for (int j = 0; j < 8; j++)
                qs += sp[j][0] * sp[j][0] + sp[j][1] * sp[j][1];
            qs += __shfl_xor_sync(0xffffffffu, qs, 1);
            qs += __shfl_xor_sync(0xffffffffu, qs, 2);
            if (lane == 0) scr[SQP + rg * 4 + cg] = qs;

            if (it < RITERS - 1) {
                // UNSCALED agree partials (scale applied after the barrier)
                float ap[2][2] = {{0.f, 0.f}, {0.f, 0.f}};
                #pragma unroll
                for (int j = 0; j < 8; j++) {
                    float s0 = sp[j][0], s1 = sp[j][1];
                    ap[0][0] += c[0][j][0] * s0 + c[0][j][1] * s1;
                    ap[0][1] += c[0][j][2] * s0 + c[0][j][3] * s1;
                    ap[1][0] += c[1][j][0] * s0 + c[1][j][1] * s1;
                    ap[1][1] += c[1][j][2] * s0 + c[1][j][3] * s1;
                }
                #pragma unroll
                for (int mt = 0; mt < 2; mt++)
                    #pragma unroll
                    for (int h = 0; h < 2; h++) {
                        float a = ap[mt][h];
                        a += __shfl_xor_sync(0xffffffffu, a, 1);
                        a += __shfl_xor_sync(0xffffffffu, a, 2);
                        if (qc == 0) {
                            int n = mt * 16 + qr + h * 8;
                            scr[AGR + rg * 128 + n * 4 + cg] = a;
                        }
                    }
            }
            bar_half(half);   // [one bar per iteration]

            float4 q4 = *(const float4*)&scr[SQP + rg * 4];
            float t4 = q4.x + q4.y + q4.z + q4.w;
            float scale = t4 / ((1.0f + t4) * sqrtf(t4 + 1e-9f));

            if (it < RITERS - 1) {
                // every warp updates its register b_ij itself (redundant, consistent)
                float4 ag = *(const float4*)&scr[AGR + rg * 128 + lane * 4];
                bij += scale * (ag.x + ag.y + ag.z + ag.w);
            } else {
                // final iter: stage v into smem for coalesced output
                #pragma unroll
                for (int j = 0; j < 8; j++)
                    if (qr == j) {
                        float2 vv = make_float2(scale * sp[j][0], scale * sp[j][1]);
                        *(float2*)&scr[S_V + rg * 256 + cg * 64 + j * 8 + qc * 2] = vv;
                    }
            }
        }

        bar_half(half);   // v staged
        out_poses[(size_t)b0 * Dout + htid]       = scr[S_V + htid];
        out_poses[(size_t)(b0 + 1) * Dout + htid] = scr[S_V + 256 + htid];
        if (cg == 0)
            out_c[(size_t)(b0 + rg) * Ncap + lane] = cval;
        // no trailing barrier needed: next writes to S_V/S_NRM happen only after
        // the next unit's own barriers, which all warps reach after these reads.
    }
}

extern "C" void kernel_launch(void* const* d_in, const int* in_sizes, int n_in,
                              void* d_out, int out_size) {
    const float* embeds  = (const float*)d_in[0];
    const float* weights = (const float*)d_in[1];
    const float* Wg      = (const float*)d_in[2];
    const float* bg      = (const float*)d_in[3];
    float* out = (float*)d_out;

    cudaFuncSetAttribute(dyr_agg_kernel,
                         cudaFuncAttributeMaxDynamicSharedMemorySize, SMEM_BYTES);
    int sms = 148;
    cudaDeviceGetAttribute(&sms, cudaDevAttrMultiProcessorCount, 0);
    dyr_agg_kernel<<<sms, 512, SMEM_BYTES>>>(embeds, weights, Wg, bg, out);
}